// round 9
// baseline (speedup 1.0000x reference)
#include <cuda_runtime.h>
#include <cuda_bf16.h>
#include <cstdint>
#include <cstddef>

// Problem constants
#define B_   4
#define C_   384
#define S_   4096

typedef __nv_bfloat16 bf16;

// ---------------------------------------------------------------------------
// Scratch (device globals; no allocation allowed in kernel_launch)
// ---------------------------------------------------------------------------
__device__ float g_scl[B_ * S_];                          // per-pixel rms scale
__device__ bf16  g_wg [3 * C_ * C_];                      // bf16(w_qkv * gamma)
__device__ bf16  g_wp [C_ * C_];                          // bf16(w_proj)
__device__ bf16  g_xnt[(size_t)B_ * S_ * C_];             // [b][s][c] normed x
__device__ bf16  g_qkt[(size_t)B_ * S_ * 2 * C_];         // [b][s][q|k]
__device__ bf16  g_v  [(size_t)B_ * C_ * S_];             // [b][c][s]
__device__ bf16  g_P  [(size_t)B_ * S_ * S_];             // [b][i][j]
__device__ bf16  g_Ot [(size_t)B_ * S_ * C_];             // [b][s][c]
__device__ float g_OtP[(size_t)2 * B_ * S_ * C_];         // split-K partials

// ---------------------------------------------------------------------------
// PTX helpers (baseline ISA only)
// ---------------------------------------------------------------------------
#define CP_ASYNC16(dst, src) \
    asm volatile("cp.async.cg.shared.global [%0], [%1], 16;" :: "r"(dst), "l"(src))
#define CP_COMMIT() asm volatile("cp.async.commit_group;" ::: "memory")
#define CP_WAIT(n)  asm volatile("cp.async.wait_group %0;" :: "n"(n) : "memory")

__device__ __forceinline__ void ldsm4(uint32_t& r0, uint32_t& r1, uint32_t& r2,
                                      uint32_t& r3, uint32_t addr) {
    asm volatile("ldmatrix.sync.aligned.m8n8.x4.shared.b16 {%0,%1,%2,%3}, [%4];"
                 : "=r"(r0), "=r"(r1), "=r"(r2), "=r"(r3) : "r"(addr));
}

__device__ __forceinline__ void mma16(float* c, const uint32_t* a, const uint32_t* b) {
    asm volatile(
        "mma.sync.aligned.m16n8k16.row.col.f32.bf16.bf16.f32 "
        "{%0,%1,%2,%3}, {%4,%5,%6,%7}, {%8,%9}, {%0,%1,%2,%3};"
        : "+f"(c[0]), "+f"(c[1]), "+f"(c[2]), "+f"(c[3])
        : "r"(a[0]), "r"(a[1]), "r"(a[2]), "r"(a[3]), "r"(b[0]), "r"(b[1]));
}

// ---------------------------------------------------------------------------
// Prep kernels
// ---------------------------------------------------------------------------
__global__ void wg_kernel(bf16* __restrict__ wg, const float* __restrict__ w,
                          const float* __restrict__ g) {
    int i = blockIdx.x * 256 + threadIdx.x;
    if (i < 3 * C_ * C_) wg[i] = __float2bfloat16_rn(w[i] * g[i % C_]);
}

__global__ void wp_kernel(bf16* __restrict__ wp, const float* __restrict__ w) {
    int i = blockIdx.x * 256 + threadIdx.x;
    if (i < C_ * C_) wp[i] = __float2bfloat16_rn(w[i]);
}

__global__ void scale_kernel(float* __restrict__ scl, const float* __restrict__ x) {
    int s = blockIdx.x * 256 + threadIdx.x;
    int b = blockIdx.y;
    const float* xb = x + (size_t)b * C_ * S_ + s;
    float acc = 0.f;
#pragma unroll 8
    for (int c = 0; c < C_; ++c) {
        float v = xb[(size_t)c * S_];
        acc += v * v;
    }
    float l2 = sqrtf(acc);
    scl[b * S_ + s] = 19.595917942265423f / fmaxf(l2, 1e-12f);  // sqrt(384)/max(l2,eps)
}

// transpose + scale: xnt[b][s][c] = bf16(x[b][c][s] * scl[b][s])
__global__ void xnt_kernel(bf16* __restrict__ xnt, const float* __restrict__ x,
                           const float* __restrict__ scl) {
    __shared__ float t[32][33];
    int b = blockIdx.z;
    int s0 = blockIdx.x * 32, c0 = blockIdx.y * 32;
    int tx = threadIdx.x, ty = threadIdx.y;   // 32 x 8
    const float* xb = x + (size_t)b * C_ * S_;
#pragma unroll
    for (int i = 0; i < 4; ++i)
        t[ty + i * 8][tx] = xb[(size_t)(c0 + ty + i * 8) * S_ + s0 + tx];
    __syncthreads();
    bf16* o = xnt + (size_t)b * S_ * C_;
#pragma unroll
    for (int i = 0; i < 4; ++i) {
        int s = s0 + ty + i * 8;
        o[(size_t)s * C_ + c0 + tx] =
            __float2bfloat16_rn(t[tx][ty + i * 8] * scl[b * S_ + s]);
    }
}

// split-K reduction: Ot[b] = bf16(plane[2b] + plane[2b+1])
__global__ void ot_reduce(bf16* __restrict__ Ot, const float* __restrict__ part) {
    const size_t plane = (size_t)S_ * C_;
    size_t i = (size_t)(blockIdx.x * 256 + threadIdx.x) * 4;
    int b = blockIdx.y;
    float4 p0 = *(const float4*)(part + (size_t)(2 * b) * plane + i);
    float4 p1 = *(const float4*)(part + (size_t)(2 * b + 1) * plane + i);
    __nv_bfloat162 h0 = __floats2bfloat162_rn(p0.x + p1.x, p0.y + p1.y);
    __nv_bfloat162 h1 = __floats2bfloat162_rn(p0.z + p1.z, p0.w + p1.w);
    uint2 o;
    o.x = *(const uint32_t*)&h0;
    o.y = *(const uint32_t*)&h1;
    *(uint2*)(Ot + (size_t)b * plane + i) = o;
}

// ---------------------------------------------------------------------------
// Warp-MMA bf16 GEMM: D[m][n] = sum_k A[m][k]*B[n][k]
// 128x128 block tile, 8 warps (4M x 2N, warp tile 32x64), Kc=32 (2 k16 steps),
// 4-stage cp.async pipeline, cross-stage fragment double buffering.
//   EPI 0: +e2[n]  -> bf16   (qk bias)
//   EPI 1: +e2[m]  -> bf16   (v bias)
//   EPI 2: *1/sqrt(C) -> bf16 (scores)
//   EPI 4: +e2[m] + e3[m*ldc+n] -> fp32 (proj bias + residual)
//   EPI 5: plain -> fp32     (split-K partials)
// SPLITK: blockIdx.z = 2*b + h; operands offset by h*kOff along k;
//         C plane index = blockIdx.z.
// ---------------------------------------------------------------------------
#define SRB    80                    // bytes per smem row (64 data + 16 pad)
#define ATILEB (128 * SRB)           // 10240 B per operand tile
#define STGB   (2 * ATILEB)          // 20480 B per stage
#define NSTG   4

template <int EPI, int SPLITK>
__global__ __launch_bounds__(256, 2)
void mma_gemm(const bf16* __restrict__ Ag, const bf16* __restrict__ Bg,
              void* __restrict__ Cgv, int K, int lda, int ldb, int ldc,
              size_t sA, size_t sB, size_t sC,
              const float* __restrict__ e2, const float* __restrict__ e3,
              size_t e3s, int kOff)
{
    extern __shared__ __align__(16) char smem[];   // NSTG * STGB bytes

    const int tid  = threadIdx.x;
    const int lane = tid & 31, wid = tid >> 5;
    const int warpM = wid & 3, warpN = wid >> 2;
    const int zz = blockIdx.z;
    const int bb = SPLITK ? (zz >> 1) : zz;
    const int hh = SPLITK ? (zz & 1) : 0;
    const int m0 = blockIdx.y * 128, n0 = blockIdx.x * 128;

    const bf16* A  = Ag + (size_t)bb * sA + (size_t)m0 * lda + (size_t)hh * kOff;
    const bf16* Bp = Bg + (size_t)bb * sB + (size_t)n0 * ldb + (size_t)hh * kOff;
    const uint32_t smB = (uint32_t)__cvta_generic_to_shared(smem);

    // global->smem loader: thread covers rows lr and lr+64, 16B at k-halfs lq
    const int lr = tid >> 2;
    const int lq = (tid & 3) * 8;                    // halfs
    const uint32_t lqB = (uint32_t)(tid & 3) * 16;   // bytes

    // ldmatrix per-thread source offsets (bytes within a stage)
    const int g = lane >> 3, r = lane & 7;
    const uint32_t aOff = (uint32_t)((warpM * 32 + (g & 1) * 8 + r) * SRB + (g >> 1) * 16);
    const uint32_t bOff = (uint32_t)(ATILEB + (warpN * 64 + (g & 1) * 8 + r) * SRB + (g >> 1) * 16);

    float acc[2][8][4];
#pragma unroll
    for (int mf = 0; mf < 2; ++mf)
#pragma unroll
        for (int nf = 0; nf < 8; ++nf)
#pragma unroll
            for (int i = 0; i < 4; ++i) acc[mf][nf][i] = 0.f;

    const int nK = K >> 5;   // Kc = 32

    auto LOAD = [&](int s) {
        const int p = s & (NSTG - 1);
        const bf16* As = A  + (size_t)lr * lda + s * 32 + lq;
        const bf16* Bs = Bp + (size_t)lr * ldb + s * 32 + lq;
        uint32_t dA = smB + (uint32_t)(p * STGB + lr * SRB) + lqB;
        uint32_t dB = dA + (uint32_t)ATILEB;
        CP_ASYNC16(dA,                As);
        CP_ASYNC16(dA + 64 * SRB,     As + (size_t)64 * lda);
        CP_ASYNC16(dB,                Bs);
        CP_ASYNC16(dB + 64 * SRB,     Bs + (size_t)64 * ldb);
    };

    // fragment double buffers: set 0 = kk0, set 1 = kk1
    uint32_t afr0[2][4], afr1[2][4];
    uint32_t bfr0[8][2], bfr1[8][2];

#define LDSM_A(dst, pb, kk)                                                     \
    _Pragma("unroll")                                                           \
    for (int mf = 0; mf < 2; ++mf)                                              \
        ldsm4((dst)[mf][0], (dst)[mf][1], (dst)[mf][2], (dst)[mf][3],           \
              (pb) + aOff + (uint32_t)(mf * 16 * SRB + (kk) * 32));

#define LDSM_B(dst, pb, kk)                                                     \
    _Pragma("unroll")                                                           \
    for (int pr = 0; pr < 4; ++pr)                                              \
        ldsm4((dst)[2 * pr][0], (dst)[2 * pr + 1][0],                           \
              (dst)[2 * pr][1], (dst)[2 * pr + 1][1],                           \
              (pb) + bOff + (uint32_t)(pr * 16 * SRB + (kk) * 32));

#define MMA_ALL(af, bf)                                                         \
    _Pragma("unroll")                                                           \
    for (int mf = 0; mf < 2; ++mf)                                              \
        _Pragma("unroll")                                                       \
        for (int nf = 0; nf < 8; ++nf)                                          \
            mma16(acc[mf][nf], (af)[mf], (bf)[nf]);

    LOAD(0); CP_COMMIT();
    LOAD(1); CP_COMMIT();
    LOAD(2); CP_COMMIT();
    CP_WAIT(2);
    __syncthreads();

    {
        const uint32_t pb0 = smB;               // stage 0 buffer
        LDSM_A(afr0, pb0, 0);
        LDSM_B(bfr0, pb0, 0);
    }

    for (int s = 0; s < nK; ++s) {
        const uint32_t pb = smB + (uint32_t)((s & (NSTG - 1)) * STGB);

        // load kk1 fragments, then MMA kk0 (LDSM hides under MMA issue)
        LDSM_A(afr1, pb, 1);
        LDSM_B(bfr1, pb, 1);
        MMA_ALL(afr0, bfr0);

        // bring stage s+3 in flight; wait for stage s+1; prefetch its kk0
        if (s + 3 < nK) LOAD(s + 3);
        CP_COMMIT();
        CP_WAIT(2);
        __syncthreads();
        if (s + 1 < nK) {
            const uint32_t pbn = smB + (uint32_t)(((s + 1) & (NSTG - 1)) * STGB);
            LDSM_A(afr0, pbn, 0);
            LDSM_B(bfr0, pbn, 0);
        }
        MMA_ALL(afr1, bfr1);
    }

    // ---- epilogue ----
    const int rBase = m0 + warpM * 32 + (lane >> 2);
    const int cBase = n0 + warpN * 64 + (lane & 3) * 2;
#pragma unroll
    for (int mf = 0; mf < 2; ++mf) {
#pragma unroll
        for (int h = 0; h < 2; ++h) {
            const int row = rBase + mf * 16 + h * 8;
            float bm = 0.f;
            if (EPI == 1 || EPI == 4) bm = e2[row];
#pragma unroll
            for (int nf = 0; nf < 8; ++nf) {
                const int col = cBase + nf * 8;
                float u0 = acc[mf][nf][2 * h];
                float u1 = acc[mf][nf][2 * h + 1];
                float2 o;
                if (EPI == 0) {
                    float2 bn = *(const float2*)(e2 + col);
                    o.x = u0 + bn.x; o.y = u1 + bn.y;
                } else if (EPI == 1) {
                    o.x = u0 + bm; o.y = u1 + bm;
                } else if (EPI == 2) {
                    const float sc = 0.05103103630798288f;   // 1/sqrt(384)
                    o.x = u0 * sc; o.y = u1 * sc;
                } else if (EPI == 5) {
                    o.x = u0; o.y = u1;
                } else {
                    const float* e3row = e3 + (size_t)bb * e3s + (size_t)row * ldc;
                    float2 rx = *(const float2*)(e3row + col);
                    o.x = u0 + bm + rx.x; o.y = u1 + bm + rx.y;
                }
                if (EPI == 4 || EPI == 5) {
                    float* Crow = (float*)Cgv + (size_t)zz * sC + (size_t)row * ldc;
                    *(float2*)(Crow + col) = o;
                } else {
                    bf16* Crow = (bf16*)Cgv + (size_t)zz * sC + (size_t)row * ldc;
                    __nv_bfloat162 hv = __floats2bfloat162_rn(o.x, o.y);
                    *(__nv_bfloat162*)(Crow + col) = hv;
                }
            }
        }
    }
#undef LDSM_A
#undef LDSM_B
#undef MMA_ALL
}

// ---------------------------------------------------------------------------
// Row softmax over 4096 bf16 columns, one block (256 thr) per row.
// ---------------------------------------------------------------------------
__global__ void softmax_kernel(bf16* __restrict__ P) {
    uint4* p = reinterpret_cast<uint4*>(P + (size_t)blockIdx.x * S_);
    const int t = threadIdx.x;

    uint4 u[2] = { p[t], p[t + 256] };
    float f[16];
#pragma unroll
    for (int i = 0; i < 2; ++i) {
        const uint32_t* w = (const uint32_t*)&u[i];
#pragma unroll
        for (int j = 0; j < 4; ++j) {
            float2 d = __bfloat1622float2(*(const __nv_bfloat162*)&w[j]);
            f[i * 8 + 2 * j] = d.x;
            f[i * 8 + 2 * j + 1] = d.y;
        }
    }

    float mx = -3.4e38f;
#pragma unroll
    for (int i = 0; i < 16; ++i) mx = fmaxf(mx, f[i]);

    __shared__ float redMax[8];
    __shared__ float redSum[8];
#pragma unroll
    for (int o = 16; o > 0; o >>= 1)
        mx = fmaxf(mx, __shfl_xor_sync(0xffffffffu, mx, o));
    if ((t & 31) == 0) redMax[t >> 5] = mx;
    __syncthreads();
    mx = redMax[0];
#pragma unroll
    for (int w = 1; w < 8; ++w) mx = fmaxf(mx, redMax[w]);

    float sum = 0.f;
#pragma unroll
    for (int i = 0; i < 16; ++i) {
        f[i] = __expf(f[i] - mx);
        sum += f[i];
    }
#pragma unroll
    for (int o = 16; o > 0; o >>= 1)
        sum += __shfl_xor_sync(0xffffffffu, sum, o);
    if ((t & 31) == 0) redSum[t >> 5] = sum;
    __syncthreads();
    sum = (redSum[0] + redSum[1]) + (redSum[2] + redSum[3]) +
          (redSum[4] + redSum[5]) + (redSum[6] + redSum[7]);
    float inv = 1.f / sum;

#pragma unroll
    for (int i = 0; i < 2; ++i) {
        uint32_t* w = (uint32_t*)&u[i];
#pragma unroll
        for (int j = 0; j < 4; ++j) {
            __nv_bfloat162 hv = __floats2bfloat162_rn(f[i * 8 + 2 * j] * inv,
                                                      f[i * 8 + 2 * j + 1] * inv);
            w[j] = *(const uint32_t*)&hv;
        }
    }
    p[t] = u[0];
    p[t + 256] = u[1];
}

// ---------------------------------------------------------------------------
// Launch
// ---------------------------------------------------------------------------
extern "C" void kernel_launch(void* const* d_in, const int* in_sizes, int n_in,
                              void* d_out, int out_size) {
    const float* x      = (const float*)d_in[0];   // [4,384,64,64]
    const float* gamma  = (const float*)d_in[1];   // [384]
    const float* w_qkv  = (const float*)d_in[2];   // [1152,384]
    const float* b_qkv  = (const float*)d_in[3];   // [1152]
    const float* w_proj = (const float*)d_in[4];   // [384,384]
    const float* b_proj = (const float*)d_in[5];   // [384]
    float* out = (float*)d_out;                    // [4,384,64,64]

    float *scl, *otp;
    bf16 *wg, *wp, *xnt, *qkt, *v, *P, *Ot;
    cudaGetSymbolAddress((void**)&scl, g_scl);
    cudaGetSymbolAddress((void**)&wg,  g_wg);
    cudaGetSymbolAddress((void**)&wp,  g_wp);
    cudaGetSymbolAddress((void**)&xnt, g_xnt);
    cudaGetSymbolAddress((void**)&qkt, g_qkt);
    cudaGetSymbolAddress((void**)&v,   g_v);
    cudaGetSymbolAddress((void**)&P,   g_P);
    cudaGetSymbolAddress((void**)&Ot,  g_Ot);
    cudaGetSymbolAddress((void**)&otp, g_OtP);

    const int SMEM_DYN = NSTG * STGB;   // 81920 bytes
    cudaFuncSetAttribute((const void*)mma_gemm<0,0>, cudaFuncAttributeMaxDynamicSharedMemorySize, SMEM_DYN);
    cudaFuncSetAttribute((const void*)mma_gemm<1,0>, cudaFuncAttributeMaxDynamicSharedMemorySize, SMEM_DYN);
    cudaFuncSetAttribute((const void*)mma_gemm<2,0>, cudaFuncAttributeMaxDynamicSharedMemorySize, SMEM_DYN);
    cudaFuncSetAttribute((const void*)mma_gemm<4,0>, cudaFuncAttributeMaxDynamicSharedMemorySize, SMEM_DYN);
    cudaFuncSetAttribute((const void*)mma_gemm<5,1>, cudaFuncAttributeMaxDynamicSharedMemorySize, SMEM_DYN);

    // 1) fold gamma into w_qkv (bf16); convert w_proj (bf16)
    wg_kernel<<<(3 * C_ * C_ + 255) / 256, 256>>>(wg, w_qkv, gamma);
    wp_kernel<<<(C_ * C_ + 255) / 256, 256>>>(wp, w_proj);
    // 2) per-pixel rms scale
    scale_kernel<<<dim3(S_ / 256, B_), 256>>>(scl, x);
    // 3) xnt[b][s][c] = bf16(x[b][c][s] * scl)
    xnt_kernel<<<dim3(S_ / 32, C_ / 32, B_), dim3(32, 8)>>>(xnt, x, scl);
    // 4) qk_t[b][s][o] = xnt @ wg[0:768]^T + b_qkv[o]      M=4096 N=768 K=384
    mma_gemm<0,0><<<dim3(6, 32, B_), 256, SMEM_DYN>>>(
        xnt, wg, qkt, C_, C_, C_, 2 * C_,
        (size_t)S_ * C_, 0, (size_t)S_ * 2 * C_, b_qkv, nullptr, 0, 0);
    // 5) v[b][c][s] = wg[768:] @ xnt^T + b_qkv[768+c]      M=384 N=4096 K=384
    mma_gemm<1,0><<<dim3(32, 3, B_), 256, SMEM_DYN>>>(
        wg + (size_t)2 * C_ * C_, xnt, v, C_, C_, C_, S_,
        0, (size_t)S_ * C_, (size_t)C_ * S_, b_qkv + 2 * C_, nullptr, 0, 0);
    // 6) P[b][i][j] = q_i . k_j / sqrt(C)                  M=N=4096 K=384
    mma_gemm<2,0><<<dim3(32, 32, B_), 256, SMEM_DYN>>>(
        qkt, qkt + C_, P, C_, 2 * C_, 2 * C_, S_,
        (size_t)S_ * 2 * C_, (size_t)S_ * 2 * C_, (size_t)S_ * S_, nullptr, nullptr, 0, 0);
    // 7) softmax rows
    softmax_kernel<<<B_ * S_, 256>>>(P);
    // 8) split-K AV: partials[2b+h][i][c] = P[:, h-half] @ v[:, h-half]^T
    //    M=4096 N=384 K=2048 per half, 768 CTAs in one launch
    mma_gemm<5,1><<<dim3(3, 32, 2 * B_), 256, SMEM_DYN>>>(
        P, v, otp, S_ / 2, S_, S_, C_,
        (size_t)S_ * S_, (size_t)C_ * S_, (size_t)S_ * C_,
        nullptr, nullptr, 0, S_ / 2);
    // 8b) Ot = bf16(partial0 + partial1)
    ot_reduce<<<dim3(S_ * C_ / 1024, B_), 256>>>(Ot, otp);
    // 9) out[b][o][s] = Wp @ Ot^T + b_proj[o] + x          M=384 N=4096 K=384
    mma_gemm<4,0><<<dim3(32, 3, B_), 256, SMEM_DYN>>>(
        wp, Ot, out, C_, C_, C_, S_,
        0, (size_t)S_ * C_, (size_t)C_ * S_, b_proj, x, (size_t)C_ * S_, 0);
}

// round 10
// speedup vs baseline: 1.0414x; 1.0414x over previous
#include <cuda_runtime.h>
#include <cuda_bf16.h>
#include <cstdint>
#include <cstddef>

// Problem constants
#define B_   4
#define C_   384
#define S_   4096

typedef __nv_bfloat16 bf16;

// ---------------------------------------------------------------------------
// Scratch (device globals; no allocation allowed in kernel_launch)
// ---------------------------------------------------------------------------
__device__ float g_scl[B_ * S_];                          // per-pixel rms scale
__device__ bf16  g_wg [3 * C_ * C_];                      // bf16(w_qkv * gamma)
__device__ bf16  g_wp [C_ * C_];                          // bf16(w_proj)
__device__ bf16  g_xnt[(size_t)B_ * S_ * C_];             // [b][s][c] normed x
__device__ bf16  g_qkt[(size_t)B_ * S_ * 2 * C_];         // [b][s][q|k]
__device__ bf16  g_v  [(size_t)B_ * C_ * S_];             // [b][c][s]
__device__ bf16  g_P  [(size_t)B_ * S_ * S_];             // [b][i][j]
__device__ bf16  g_Ot [(size_t)B_ * S_ * C_];             // [b][s][c]
__device__ float g_OtP[(size_t)2 * B_ * S_ * C_];         // split-K partials

// ---------------------------------------------------------------------------
// PTX helpers (baseline ISA only)
// ---------------------------------------------------------------------------
#define CP_ASYNC16(dst, src) \
    asm volatile("cp.async.cg.shared.global [%0], [%1], 16;" :: "r"(dst), "l"(src))
#define CP_COMMIT() asm volatile("cp.async.commit_group;" ::: "memory")
#define CP_WAIT(n)  asm volatile("cp.async.wait_group %0;" :: "n"(n) : "memory")

__device__ __forceinline__ void ldsm4(uint32_t& r0, uint32_t& r1, uint32_t& r2,
                                      uint32_t& r3, uint32_t addr) {
    asm volatile("ldmatrix.sync.aligned.m8n8.x4.shared.b16 {%0,%1,%2,%3}, [%4];"
                 : "=r"(r0), "=r"(r1), "=r"(r2), "=r"(r3) : "r"(addr));
}

__device__ __forceinline__ void mma16(float* c, const uint32_t* a, const uint32_t* b) {
    asm volatile(
        "mma.sync.aligned.m16n8k16.row.col.f32.bf16.bf16.f32 "
        "{%0,%1,%2,%3}, {%4,%5,%6,%7}, {%8,%9}, {%0,%1,%2,%3};"
        : "+f"(c[0]), "+f"(c[1]), "+f"(c[2]), "+f"(c[3])
        : "r"(a[0]), "r"(a[1]), "r"(a[2]), "r"(a[3]), "r"(b[0]), "r"(b[1]));
}

// ---------------------------------------------------------------------------
// Prep kernels
// ---------------------------------------------------------------------------
__global__ void wg_kernel(bf16* __restrict__ wg, const float* __restrict__ w,
                          const float* __restrict__ g) {
    int i = blockIdx.x * 256 + threadIdx.x;
    if (i < 3 * C_ * C_) wg[i] = __float2bfloat16_rn(w[i] * g[i % C_]);
}

__global__ void wp_kernel(bf16* __restrict__ wp, const float* __restrict__ w) {
    int i = blockIdx.x * 256 + threadIdx.x;
    if (i < C_ * C_) wp[i] = __float2bfloat16_rn(w[i]);
}

__global__ void scale_kernel(float* __restrict__ scl, const float* __restrict__ x) {
    int s = blockIdx.x * 256 + threadIdx.x;
    int b = blockIdx.y;
    const float* xb = x + (size_t)b * C_ * S_ + s;
    float acc = 0.f;
#pragma unroll 8
    for (int c = 0; c < C_; ++c) {
        float v = xb[(size_t)c * S_];
        acc += v * v;
    }
    float l2 = sqrtf(acc);
    scl[b * S_ + s] = 19.595917942265423f / fmaxf(l2, 1e-12f);  // sqrt(384)/max(l2,eps)
}

// transpose + scale: xnt[b][s][c] = bf16(x[b][c][s] * scl[b][s])
__global__ void xnt_kernel(bf16* __restrict__ xnt, const float* __restrict__ x,
                           const float* __restrict__ scl) {
    __shared__ float t[32][33];
    int b = blockIdx.z;
    int s0 = blockIdx.x * 32, c0 = blockIdx.y * 32;
    int tx = threadIdx.x, ty = threadIdx.y;   // 32 x 8
    const float* xb = x + (size_t)b * C_ * S_;
#pragma unroll
    for (int i = 0; i < 4; ++i)
        t[ty + i * 8][tx] = xb[(size_t)(c0 + ty + i * 8) * S_ + s0 + tx];
    __syncthreads();
    bf16* o = xnt + (size_t)b * S_ * C_;
#pragma unroll
    for (int i = 0; i < 4; ++i) {
        int s = s0 + ty + i * 8;
        o[(size_t)s * C_ + c0 + tx] =
            __float2bfloat16_rn(t[tx][ty + i * 8] * scl[b * S_ + s]);
    }
}

// split-K reduction: Ot[b] = bf16(plane[2b] + plane[2b+1])
__global__ void ot_reduce(bf16* __restrict__ Ot, const float* __restrict__ part) {
    const size_t plane = (size_t)S_ * C_;
    size_t i = (size_t)(blockIdx.x * 256 + threadIdx.x) * 4;
    int b = blockIdx.y;
    float4 p0 = *(const float4*)(part + (size_t)(2 * b) * plane + i);
    float4 p1 = *(const float4*)(part + (size_t)(2 * b + 1) * plane + i);
    __nv_bfloat162 h0 = __floats2bfloat162_rn(p0.x + p1.x, p0.y + p1.y);
    __nv_bfloat162 h1 = __floats2bfloat162_rn(p0.z + p1.z, p0.w + p1.w);
    uint2 o;
    o.x = *(const uint32_t*)&h0;
    o.y = *(const uint32_t*)&h1;
    *(uint2*)(Ot + (size_t)b * plane + i) = o;
}

// ---------------------------------------------------------------------------
// Warp-MMA bf16 GEMM: D[m][n] = sum_k A[m][k]*B[n][k]
// 128x128 block tile, 8 warps (4M x 2N, warp tile 32x64), Kc=32 (2 k16 steps),
// 4-stage cp.async pipeline, ldmatrix operand fetch, fp32 accumulate.
// (R8-proven mainloop: single fragment set, one barrier per stage.)
//   EPI 0: +e2[n]  -> bf16   (qk bias)
//   EPI 1: +e2[m]  -> bf16   (v bias)
//   EPI 2: *1/sqrt(C) -> bf16 (scores)
//   EPI 4: +e2[m] + e3[m*ldc+n] -> fp32 (proj bias + residual)
//   EPI 5: plain -> fp32     (split-K partials)
// SPLITK: blockIdx.z = 2*b + h; operands offset by h*kOff along k;
//         C plane index = blockIdx.z.
// ---------------------------------------------------------------------------
#define SRB    80                    // bytes per smem row (64 data + 16 pad)
#define ATILEB (128 * SRB)           // 10240 B per operand tile
#define STGB   (2 * ATILEB)          // 20480 B per stage
#define NSTG   4

template <int EPI, int SPLITK>
__global__ __launch_bounds__(256)
void mma_gemm(const bf16* __restrict__ Ag, const bf16* __restrict__ Bg,
              void* __restrict__ Cgv, int K, int lda, int ldb, int ldc,
              size_t sA, size_t sB, size_t sC,
              const float* __restrict__ e2, const float* __restrict__ e3,
              size_t e3s, int kOff)
{
    extern __shared__ __align__(16) char smem[];   // NSTG * STGB bytes

    const int tid  = threadIdx.x;
    const int lane = tid & 31, wid = tid >> 5;
    const int warpM = wid & 3, warpN = wid >> 2;
    const int zz = blockIdx.z;
    const int bb = SPLITK ? (zz >> 1) : zz;
    const int hh = SPLITK ? (zz & 1) : 0;
    const int m0 = blockIdx.y * 128, n0 = blockIdx.x * 128;

    const bf16* A  = Ag + (size_t)bb * sA + (size_t)m0 * lda + (size_t)hh * kOff;
    const bf16* Bp = Bg + (size_t)bb * sB + (size_t)n0 * ldb + (size_t)hh * kOff;
    const uint32_t smB = (uint32_t)__cvta_generic_to_shared(smem);

    // global->smem loader: thread covers rows lr and lr+64, 16B at k-halfs lq
    const int lr = tid >> 2;
    const int lq = (tid & 3) * 8;                    // halfs
    const uint32_t lqB = (uint32_t)(tid & 3) * 16;   // bytes

    // ldmatrix per-thread source offsets (bytes within a stage)
    const int g = lane >> 3, r = lane & 7;
    const uint32_t aOff = (uint32_t)((warpM * 32 + (g & 1) * 8 + r) * SRB + (g >> 1) * 16);
    const uint32_t bOff = (uint32_t)(ATILEB + (warpN * 64 + (g & 1) * 8 + r) * SRB + (g >> 1) * 16);

    float acc[2][8][4];
#pragma unroll
    for (int mf = 0; mf < 2; ++mf)
#pragma unroll
        for (int nf = 0; nf < 8; ++nf)
#pragma unroll
            for (int i = 0; i < 4; ++i) acc[mf][nf][i] = 0.f;

    const int nK = K >> 5;   // Kc = 32

    auto LOAD = [&](int s) {
        const int p = s & (NSTG - 1);
        const bf16* As = A  + (size_t)lr * lda + s * 32 + lq;
        const bf16* Bs = Bp + (size_t)lr * ldb + s * 32 + lq;
        uint32_t dA = smB + (uint32_t)(p * STGB + lr * SRB) + lqB;
        uint32_t dB = dA + (uint32_t)ATILEB;
        CP_ASYNC16(dA,                As);
        CP_ASYNC16(dA + 64 * SRB,     As + (size_t)64 * lda);
        CP_ASYNC16(dB,                Bs);
        CP_ASYNC16(dB + 64 * SRB,     Bs + (size_t)64 * ldb);
    };

    LOAD(0); CP_COMMIT();
    LOAD(1); CP_COMMIT();
    LOAD(2); CP_COMMIT();

    for (int s = 0; s < nK; ++s) {
        CP_WAIT(2);              // stage s landed
        __syncthreads();         // visibility + buffer-reuse fence
        if (s + 3 < nK) LOAD(s + 3);
        CP_COMMIT();             // empty group at tail keeps counts uniform

        const uint32_t pb = smB + (uint32_t)((s & (NSTG - 1)) * STGB);
#pragma unroll
        for (int kk = 0; kk < 2; ++kk) {      // two k16 steps per stage
            uint32_t afr[2][4], bfr[8][2];
#pragma unroll
            for (int mf = 0; mf < 2; ++mf)
                ldsm4(afr[mf][0], afr[mf][1], afr[mf][2], afr[mf][3],
                      pb + aOff + (uint32_t)(mf * 16 * SRB + kk * 32));
#pragma unroll
            for (int pr = 0; pr < 4; ++pr)
                ldsm4(bfr[2 * pr][0], bfr[2 * pr + 1][0],
                      bfr[2 * pr][1], bfr[2 * pr + 1][1],
                      pb + bOff + (uint32_t)(pr * 16 * SRB + kk * 32));
#pragma unroll
            for (int mf = 0; mf < 2; ++mf)
#pragma unroll
                for (int nf = 0; nf < 8; ++nf)
                    mma16(acc[mf][nf], afr[mf], bfr[nf]);
        }
    }

    // ---- epilogue ----
    const int rBase = m0 + warpM * 32 + (lane >> 2);
    const int cBase = n0 + warpN * 64 + (lane & 3) * 2;
#pragma unroll
    for (int mf = 0; mf < 2; ++mf) {
#pragma unroll
        for (int h = 0; h < 2; ++h) {
            const int row = rBase + mf * 16 + h * 8;
            float bm = 0.f;
            if (EPI == 1 || EPI == 4) bm = e2[row];
#pragma unroll
            for (int nf = 0; nf < 8; ++nf) {
                const int col = cBase + nf * 8;
                float u0 = acc[mf][nf][2 * h];
                float u1 = acc[mf][nf][2 * h + 1];
                float2 o;
                if (EPI == 0) {
                    float2 bn = *(const float2*)(e2 + col);
                    o.x = u0 + bn.x; o.y = u1 + bn.y;
                } else if (EPI == 1) {
                    o.x = u0 + bm; o.y = u1 + bm;
                } else if (EPI == 2) {
                    const float sc = 0.05103103630798288f;   // 1/sqrt(384)
                    o.x = u0 * sc; o.y = u1 * sc;
                } else if (EPI == 5) {
                    o.x = u0; o.y = u1;
                } else {
                    const float* e3row = e3 + (size_t)bb * e3s + (size_t)row * ldc;
                    float2 rx = *(const float2*)(e3row + col);
                    o.x = u0 + bm + rx.x; o.y = u1 + bm + rx.y;
                }
                if (EPI == 4 || EPI == 5) {
                    float* Crow = (float*)Cgv + (size_t)zz * sC + (size_t)row * ldc;
                    *(float2*)(Crow + col) = o;
                } else {
                    bf16* Crow = (bf16*)Cgv + (size_t)zz * sC + (size_t)row * ldc;
                    __nv_bfloat162 hv = __floats2bfloat162_rn(o.x, o.y);
                    *(__nv_bfloat162*)(Crow + col) = hv;
                }
            }
        }
    }
}

// ---------------------------------------------------------------------------
// Row softmax over 4096 bf16 columns, one block (256 thr) per row.
// ---------------------------------------------------------------------------
__global__ void softmax_kernel(bf16* __restrict__ P) {
    uint4* p = reinterpret_cast<uint4*>(P + (size_t)blockIdx.x * S_);
    const int t = threadIdx.x;

    uint4 u[2] = { p[t], p[t + 256] };
    float f[16];
#pragma unroll
    for (int i = 0; i < 2; ++i) {
        const uint32_t* w = (const uint32_t*)&u[i];
#pragma unroll
        for (int j = 0; j < 4; ++j) {
            float2 d = __bfloat1622float2(*(const __nv_bfloat162*)&w[j]);
            f[i * 8 + 2 * j] = d.x;
            f[i * 8 + 2 * j + 1] = d.y;
        }
    }

    float mx = -3.4e38f;
#pragma unroll
    for (int i = 0; i < 16; ++i) mx = fmaxf(mx, f[i]);

    __shared__ float redMax[8];
    __shared__ float redSum[8];
#pragma unroll
    for (int o = 16; o > 0; o >>= 1)
        mx = fmaxf(mx, __shfl_xor_sync(0xffffffffu, mx, o));
    if ((t & 31) == 0) redMax[t >> 5] = mx;
    __syncthreads();
    mx = redMax[0];
#pragma unroll
    for (int w = 1; w < 8; ++w) mx = fmaxf(mx, redMax[w]);

    float sum = 0.f;
#pragma unroll
    for (int i = 0; i < 16; ++i) {
        f[i] = __expf(f[i] - mx);
        sum += f[i];
    }
#pragma unroll
    for (int o = 16; o > 0; o >>= 1)
        sum += __shfl_xor_sync(0xffffffffu, sum, o);
    if ((t & 31) == 0) redSum[t >> 5] = sum;
    __syncthreads();
    sum = (redSum[0] + redSum[1]) + (redSum[2] + redSum[3]) +
          (redSum[4] + redSum[5]) + (redSum[6] + redSum[7]);
    float inv = 1.f / sum;

#pragma unroll
    for (int i = 0; i < 2; ++i) {
        uint32_t* w = (uint32_t*)&u[i];
#pragma unroll
        for (int j = 0; j < 4; ++j) {
            __nv_bfloat162 hv = __floats2bfloat162_rn(f[i * 8 + 2 * j] * inv,
                                                      f[i * 8 + 2 * j + 1] * inv);
            w[j] = *(const uint32_t*)&hv;
        }
    }
    p[t] = u[0];
    p[t + 256] = u[1];
}

// ---------------------------------------------------------------------------
// Launch
// ---------------------------------------------------------------------------
extern "C" void kernel_launch(void* const* d_in, const int* in_sizes, int n_in,
                              void* d_out, int out_size) {
    const float* x      = (const float*)d_in[0];   // [4,384,64,64]
    const float* gamma  = (const float*)d_in[1];   // [384]
    const float* w_qkv  = (const float*)d_in[2];   // [1152,384]
    const float* b_qkv  = (const float*)d_in[3];   // [1152]
    const float* w_proj = (const float*)d_in[4];   // [384,384]
    const float* b_proj = (const float*)d_in[5];   // [384]
    float* out = (float*)d_out;                    // [4,384,64,64]

    float *scl, *otp;
    bf16 *wg, *wp, *xnt, *qkt, *v, *P, *Ot;
    cudaGetSymbolAddress((void**)&scl, g_scl);
    cudaGetSymbolAddress((void**)&wg,  g_wg);
    cudaGetSymbolAddress((void**)&wp,  g_wp);
    cudaGetSymbolAddress((void**)&xnt, g_xnt);
    cudaGetSymbolAddress((void**)&qkt, g_qkt);
    cudaGetSymbolAddress((void**)&v,   g_v);
    cudaGetSymbolAddress((void**)&P,   g_P);
    cudaGetSymbolAddress((void**)&Ot,  g_Ot);
    cudaGetSymbolAddress((void**)&otp, g_OtP);

    const int SMEM_DYN = NSTG * STGB;   // 81920 bytes
    cudaFuncSetAttribute((const void*)mma_gemm<0,0>, cudaFuncAttributeMaxDynamicSharedMemorySize, SMEM_DYN);
    cudaFuncSetAttribute((const void*)mma_gemm<1,0>, cudaFuncAttributeMaxDynamicSharedMemorySize, SMEM_DYN);
    cudaFuncSetAttribute((const void*)mma_gemm<2,0>, cudaFuncAttributeMaxDynamicSharedMemorySize, SMEM_DYN);
    cudaFuncSetAttribute((const void*)mma_gemm<4,0>, cudaFuncAttributeMaxDynamicSharedMemorySize, SMEM_DYN);
    cudaFuncSetAttribute((const void*)mma_gemm<5,1>, cudaFuncAttributeMaxDynamicSharedMemorySize, SMEM_DYN);

    // 1) fold gamma into w_qkv (bf16); convert w_proj (bf16)
    wg_kernel<<<(3 * C_ * C_ + 255) / 256, 256>>>(wg, w_qkv, gamma);
    wp_kernel<<<(C_ * C_ + 255) / 256, 256>>>(wp, w_proj);
    // 2) per-pixel rms scale
    scale_kernel<<<dim3(S_ / 256, B_), 256>>>(scl, x);
    // 3) xnt[b][s][c] = bf16(x[b][c][s] * scl)
    xnt_kernel<<<dim3(S_ / 32, C_ / 32, B_), dim3(32, 8)>>>(xnt, x, scl);
    // 4) qk_t[b][s][o] = xnt @ wg[0:768]^T + b_qkv[o]      M=4096 N=768 K=384
    mma_gemm<0,0><<<dim3(6, 32, B_), 256, SMEM_DYN>>>(
        xnt, wg, qkt, C_, C_, C_, 2 * C_,
        (size_t)S_ * C_, 0, (size_t)S_ * 2 * C_, b_qkv, nullptr, 0, 0);
    // 5) v[b][c][s] = wg[768:] @ xnt^T + b_qkv[768+c]      M=384 N=4096 K=384
    mma_gemm<1,0><<<dim3(32, 3, B_), 256, SMEM_DYN>>>(
        wg + (size_t)2 * C_ * C_, xnt, v, C_, C_, C_, S_,
        0, (size_t)S_ * C_, (size_t)C_ * S_, b_qkv + 2 * C_, nullptr, 0, 0);
    // 6) P[b][i][j] = q_i . k_j / sqrt(C)                  M=N=4096 K=384
    mma_gemm<2,0><<<dim3(32, 32, B_), 256, SMEM_DYN>>>(
        qkt, qkt + C_, P, C_, 2 * C_, 2 * C_, S_,
        (size_t)S_ * 2 * C_, (size_t)S_ * 2 * C_, (size_t)S_ * S_, nullptr, nullptr, 0, 0);
    // 7) softmax rows
    softmax_kernel<<<B_ * S_, 256>>>(P);
    // 8) split-K AV: partials[2b+h][i][c] = P[:, h-half] @ v[:, h-half]^T
    //    M=4096 N=384 K=2048 per half, 768 CTAs in one launch
    mma_gemm<5,1><<<dim3(3, 32, 2 * B_), 256, SMEM_DYN>>>(
        P, v, otp, S_ / 2, S_, S_, C_,
        (size_t)S_ * S_, (size_t)C_ * S_, (size_t)S_ * C_,
        nullptr, nullptr, 0, S_ / 2);
    // 8b) Ot = bf16(partial0 + partial1)
    ot_reduce<<<dim3(S_ * C_ / 1024, B_), 256>>>(Ot, otp);
    // 9) out[b][o][s] = Wp @ Ot^T + b_proj[o] + x          M=384 N=4096 K=384
    mma_gemm<4,0><<<dim3(32, 3, B_), 256, SMEM_DYN>>>(
        wp, Ot, out, C_, C_, C_, S_,
        0, (size_t)S_ * C_, (size_t)C_ * S_, b_proj, x, (size_t)C_ * S_, 0);
}